// round 14
// baseline (speedup 1.0000x reference)
#include <cuda_runtime.h>
#include <cuda_fp16.h>
#include <math.h>
#include <stdint.h>

#define NN   50000
#define DD   16
#define FF   128
#define F4   512
#define CCLS 40

// ---- scratch (device globals: allocation-free rule) ----
__device__ __half g_G[(size_t)NN * F4];       // permuted gate preacts fp16 (51MB, L2-resident)
__device__ float  g_aggr[(size_t)NN * FF];    // LSTM output
__device__ float  g_h1[(size_t)NN * FF];      // layer-1 output
__device__ __half g_Whhp[2][F4 * FF];         // permuted Whh fp16 (i,f,o rows pre-scaled 0.5)
__device__ __half g_Wihp[2][F4 * FF];         // permuted Wih fp16 (i,f,o rows pre-scaled 0.5)
__device__ __half g_Wpp[2][FF * FF];          // projection W fp16
__device__ float  g_biasp[2][F4];             // permuted bih+bhh (i,f,o rows pre-scaled 0.5)

// ============================================================================
// helpers
// ============================================================================
__device__ __forceinline__ uint32_t smem_u32(const void* p) {
    uint32_t a;
    asm("{ .reg .u64 t; cvta.to.shared.u64 t, %1; cvt.u32.u64 %0, t; }" : "=r"(a) : "l"(p));
    return a;
}
__device__ __forceinline__ void ldsm4(uint32_t addr, uint32_t r[4]) {
    asm volatile("ldmatrix.sync.aligned.m8n8.x4.shared.b16 {%0,%1,%2,%3}, [%4];"
        : "=r"(r[0]), "=r"(r[1]), "=r"(r[2]), "=r"(r[3]) : "r"(addr));
}
__device__ __forceinline__ void mma16816(float d[4], const uint32_t a[4], uint32_t b0, uint32_t b1) {
    asm volatile("mma.sync.aligned.m16n8k16.row.col.f32.f16.f16.f32 "
        "{%0,%1,%2,%3},{%4,%5,%6,%7},{%8,%9},{%0,%1,%2,%3};"
        : "+f"(d[0]), "+f"(d[1]), "+f"(d[2]), "+f"(d[3])
        : "r"(a[0]), "r"(a[1]), "r"(a[2]), "r"(a[3]), "r"(b0), "r"(b1));
}
__device__ __forceinline__ float tna(float x) { float y; asm("tanh.approx.f32 %0, %1;" : "=f"(y) : "f"(x)); return y; }
// sigmoid with the 1/2 pre-folded into the weights: sig(x) = 0.5 + 0.5*tanh(x_scaled)
__device__ __forceinline__ float sigp(float xs) { return fmaf(tna(xs), 0.5f, 0.5f); }
__device__ __forceinline__ float h2lo(uint32_t v) { __half2 h = *(__half2*)&v; return __low2float(h); }
__device__ __forceinline__ float h2hi(uint32_t v) { __half2 h = *(__half2*)&v; return __high2float(h); }
#define BARG(id) asm volatile("bar.sync %0, 128;" :: "r"(id) : "memory")

// ============================================================================
// Gate-interleave permutation + Wp fp16 conversion — BOTH layers in one launch.
// i,f,o gate rows pre-scaled by 0.5 (exact in fp16).
// ============================================================================
__global__ void prep_permute2(
    const float* __restrict__ Wih1, const float* __restrict__ Whh1,
    const float* __restrict__ bih1, const float* __restrict__ bhh1,
    const float* __restrict__ Wp1,
    const float* __restrict__ Wih2, const float* __restrict__ Whh2,
    const float* __restrict__ bih2, const float* __restrict__ bhh2,
    const float* __restrict__ Wp2)
{
    const int L = blockIdx.y;
    const float* Wih = L ? Wih2 : Wih1;
    const float* Whh = L ? Whh2 : Whh1;
    const float* bih = L ? bih2 : bih1;
    const float* bhh = L ? bhh2 : bhh1;
    const float* Wp  = L ? Wp2  : Wp1;

    int p = blockIdx.x;                 // 0..511 permuted row
    int c = p & 63;
    int nb = p >> 6;
    int c15 = c & 15;
    int g = 2 * ((c15 >> 3) & 1) + (c15 & 1);
    int q = (c15 & 7) >> 1;
    int a = (c >> 4) & 3;
    int u = nb * 16 + 4 * a + q;
    int srow = g * FF + u;              // torch gate order i,f,g,o blocks of 128
    float scale = (g == 2) ? 1.0f : 0.5f;   // i,f,o gates: fold sigmoid's 1/2
    for (int k = threadIdx.x; k < FF; k += blockDim.x) {
        g_Wihp[L][p * FF + k] = __float2half_rn(scale * Wih[srow * FF + k]);
        g_Whhp[L][p * FF + k] = __float2half_rn(scale * Whh[srow * FF + k]);
    }
    if (p < FF)
        for (int k = threadIdx.x; k < FF; k += blockDim.x)
            g_Wpp[L][p * FF + k] = __float2half_rn(Wp[p * FF + k]);
    if (threadIdx.x == 0) g_biasp[L][p] = scale * (bih[srow] + bhh[srow]);
}

// ============================================================================
// HMMA GEMM (plain fp16 operands, fp32 accum): C = act( A@W^T (+ A2@W2^T) + b )
// CTA = 64 rows, 256 threads, ~97 KB SMEM -> 2 CTAs/SM. UNCHANGED.
// ============================================================================
#define HG_W1   0
#define HG_W2   32768
#define HG_A1H  65536
#define HG_A2H  81920
#define HG_BIAS 98304
#define HG_SMEM (98304 + 512 + 128)

template<bool RELU, bool DUAL, int NT>
__global__ __launch_bounds__(256, 2) void hgemm(
    const float* __restrict__ A,  const float* __restrict__ W,
    const float* __restrict__ A2, const float* __restrict__ W2,
    const float* __restrict__ bias,
    float* __restrict__ C, int M, int Nout)
{
    extern __shared__ char sm[];
    const int tid = threadIdx.x, w = tid >> 5, lane = tid & 31;
    const int rg = w & 3, ch = w >> 2;            // ch in {0,1}
    const int q = lane & 3, r = lane >> 2;
    const int rowBase = blockIdx.x * 64;

    for (int idx = tid; idx < NT * 16 * 16; idx += 256) {
        int row = idx >> 4, chk = idx & 15;
        int phys = chk ^ (row & 7);
        __half2 hv[4], hv2[4];
        if (row < Nout) {
            const float* s1 = W + (size_t)row * FF + chk * 8;
            #pragma unroll
            for (int e = 0; e < 4; e++) { float2 v = *(const float2*)(s1 + e * 2); hv[e] = __floats2half2_rn(v.x, v.y); }
            if (DUAL) {
                const float* s2 = W2 + (size_t)row * FF + chk * 8;
                #pragma unroll
                for (int e = 0; e < 4; e++) { float2 v = *(const float2*)(s2 + e * 2); hv2[e] = __floats2half2_rn(v.x, v.y); }
            }
        } else {
            #pragma unroll
            for (int e = 0; e < 4; e++) { hv[e] = __floats2half2_rn(0.f, 0.f); hv2[e] = hv[e]; }
        }
        *(uint4*)(sm + HG_W1 + (row * 128 + phys * 8) * 2) = *(const uint4*)hv;
        if (DUAL) *(uint4*)(sm + HG_W2 + (row * 128 + phys * 8) * 2) = *(const uint4*)hv2;
    }
    for (int i = tid; i < NT * 16; i += 256)
        *(float*)(sm + HG_BIAS + i * 4) = (i < Nout) ? bias[i] : 0.f;
    for (int idx = tid; idx < 64 * 16; idx += 256) {
        int row = idx >> 4, chk = idx & 15;
        int node = rowBase + row;
        int phys = chk ^ (row & 7);
        #pragma unroll
        for (int p = 0; p < (DUAL ? 2 : 1); p++) {
            const float* Ap = p ? A2 : A;
            __half2 hh[4];
            if (node < M) {
                float4 v0 = *(const float4*)(Ap + (size_t)node * FF + chk * 8);
                float4 v1 = *(const float4*)(Ap + (size_t)node * FF + chk * 8 + 4);
                hh[0] = __floats2half2_rn(v0.x, v0.y);
                hh[1] = __floats2half2_rn(v0.z, v0.w);
                hh[2] = __floats2half2_rn(v1.x, v1.y);
                hh[3] = __floats2half2_rn(v1.z, v1.w);
            } else {
                #pragma unroll
                for (int e = 0; e < 4; e++) hh[e] = __floats2half2_rn(0.f, 0.f);
            }
            *(uint4*)(sm + (p ? HG_A2H : HG_A1H) + (row * 128 + phys * 8) * 2) = *(const uint4*)hh;
        }
    }
    __syncthreads();

    float acc[NT / 2][2][4] = {};
    const int npass = DUAL ? 2 : 1;
    for (int p = 0; p < npass; p++) {
        const uint32_t wu  = smem_u32(sm + (p ? HG_W2  : HG_W1));
        const uint32_t ahu = smem_u32(sm + (p ? HG_A2H : HG_A1H));
        uint32_t Ah[8][4];
        int rowb = rg * 16 + (lane & 7) + ((lane >> 3) & 1) * 8;
        #pragma unroll
        for (int kt = 0; kt < 8; kt++) {
            int chk = 2 * kt + (lane >> 4);
            int phys = chk ^ (rowb & 7);
            ldsm4(ahu + rowb * 256 + phys * 16, Ah[kt]);
        }
        #pragma unroll
        for (int j = 0; j < NT / 2; j++) {
            int s = ch * (NT / 2) + j;
            #pragma unroll
            for (int sp = 0; sp < 2; sp++) {
                int rowbB = s * 16 + sp * 8 + (lane & 7);
                uint32_t b[4][4];
                #pragma unroll
                for (int ktp = 0; ktp < 4; ktp++) {
                    int chk = 4 * ktp + (lane >> 3);
                    int phys = chk ^ (rowbB & 7);
                    ldsm4(wu + rowbB * 256 + phys * 16, b[ktp]);
                }
                #pragma unroll
                for (int kt = 0; kt < 8; kt++)
                    mma16816(acc[j][sp], Ah[kt], b[kt >> 1][(kt & 1) * 2], b[kt >> 1][(kt & 1) * 2 + 1]);
            }
        }
    }

    const float* bs = (const float*)(sm + HG_BIAS);
    #pragma unroll
    for (int j = 0; j < NT / 2; j++) {
        int s = ch * (NT / 2) + j;
        #pragma unroll
        for (int sp = 0; sp < 2; sp++) {
            int col = s * 16 + sp * 8 + 2 * q;
            if (col >= Nout) continue;
            float b0 = bs[col], b1 = bs[col + 1];
            #pragma unroll
            for (int rp = 0; rp < 2; rp++) {
                int row = rowBase + rg * 16 + r + rp * 8;
                if (row >= M) continue;
                float v0 = acc[j][sp][rp * 2 + 0] + b0;
                float v1 = acc[j][sp][rp * 2 + 1] + b1;
                if (RELU) { v0 = fmaxf(v0, 0.f); v1 = fmaxf(v1, 0.f); }
                *(float2*)(C + (size_t)row * Nout + col) = make_float2(v0, v1);
            }
        }
    }
}

// ============================================================================
// FUSED projection + G precompute (HMMA), hi/lo compensated. UNCHANGED (R10).
// ============================================================================
#define FZ_WIH  0
#define FZ_WP   131072
#define FZ_AH   163840
#define FZ_AL   196608
#define FZ_BIAS 229376
#define FZ_BP   231424
#define FZ_SMEM (231424 + 512)

__global__ __launch_bounds__(512, 1) void gfused(
    const float* __restrict__ x, const float* __restrict__ bp,
    const __half* __restrict__ WihL, const __half* __restrict__ WpL,
    const float* __restrict__ biaspL,
    __half2* __restrict__ G2)
{
    extern __shared__ char sm[];
    const uint32_t wih_u = smem_u32(sm + FZ_WIH);
    const uint32_t wp_u  = smem_u32(sm + FZ_WP);
    const uint32_t ah_u  = smem_u32(sm + FZ_AH);
    const uint32_t al_u  = smem_u32(sm + FZ_AL);
    float* bs  = (float*)(sm + FZ_BIAS);
    float* bps = (float*)(sm + FZ_BP);
    const int tid = threadIdx.x, w = tid >> 5, lane = tid & 31;
    const int rg = w & 7, ch = w >> 3;           // rg 0..7 (16-row groups), ch 0..1
    const int q = lane & 3, r = lane >> 2;
    const int nodeBase = blockIdx.x * 128;

    for (int idx = tid; idx < 8192; idx += 512) {
        int row = idx >> 4, chk = idx & 15;
        int phys = chk ^ (row & 7);
        *(uint4*)(sm + FZ_WIH + (row * 128 + phys * 8) * 2) = *(const uint4*)(WihL + row * 128 + chk * 8);
    }
    for (int idx = tid; idx < 2048; idx += 512) {
        int row = idx >> 4, chk = idx & 15;
        int phys = chk ^ (row & 7);
        *(uint4*)(sm + FZ_WP + (row * 128 + phys * 8) * 2) = *(const uint4*)(WpL + row * 128 + chk * 8);
    }
    for (int i = tid; i < F4; i += 512) bs[i] = biaspL[i];
    if (tid < FF) bps[tid] = bp[tid];
    for (int idx = tid; idx < 2048; idx += 512) {
        int row = idx >> 4, chk = idx & 15;
        int node = nodeBase + row;
        float v[8];
        if (node < NN) {
            float4 v0 = *(const float4*)(x + (size_t)node * FF + chk * 8);
            float4 v1 = *(const float4*)(x + (size_t)node * FF + chk * 8 + 4);
            v[0]=v0.x; v[1]=v0.y; v[2]=v0.z; v[3]=v0.w; v[4]=v1.x; v[5]=v1.y; v[6]=v1.z; v[7]=v1.w;
        } else {
            #pragma unroll
            for (int e = 0; e < 8; e++) v[e] = 0.f;
        }
        __half2 hh[4], hl[4];
        #pragma unroll
        for (int e = 0; e < 4; e++) {
            __half h0 = __float2half_rn(v[2*e]), h1 = __float2half_rn(v[2*e+1]);
            hh[e] = __halves2half2(h0, h1);
            hl[e] = __halves2half2(__float2half_rn(v[2*e] - __half2float(h0)),
                                   __float2half_rn(v[2*e+1] - __half2float(h1)));
        }
        int phys = chk ^ (row & 7);
        *(uint4*)(sm + FZ_AH + (row * 128 + phys * 8) * 2) = *(const uint4*)hh;
        *(uint4*)(sm + FZ_AL + (row * 128 + phys * 8) * 2) = *(const uint4*)hl;
    }
    __syncthreads();

    // ---- GEMM1: xp = relu(x @ Wp^T + bp) ----
    {
        uint32_t Ah[8][4], Al[8][4];
        int rowb = rg * 16 + (lane & 7) + ((lane >> 3) & 1) * 8;
        #pragma unroll
        for (int kt = 0; kt < 8; kt++) {
            int chk = 2 * kt + (lane >> 4);
            int phys = chk ^ (rowb & 7);
            ldsm4(ah_u + rowb * 256 + phys * 16, Ah[kt]);
            ldsm4(al_u + rowb * 256 + phys * 16, Al[kt]);
        }
        float acc[4][2][4] = {};
        #pragma unroll
        for (int j = 0; j < 4; j++) {
            int s = ch * 4 + j;
            #pragma unroll
            for (int sp = 0; sp < 2; sp++) {
                int rowbB = s * 16 + sp * 8 + (lane & 7);
                uint32_t b[4][4];
                #pragma unroll
                for (int ktp = 0; ktp < 4; ktp++) {
                    int chk = 4 * ktp + (lane >> 3);
                    int phys = chk ^ (rowbB & 7);
                    ldsm4(wp_u + rowbB * 256 + phys * 16, b[ktp]);
                }
                #pragma unroll
                for (int kt = 0; kt < 8; kt++) {
                    uint32_t b0 = b[kt >> 1][(kt & 1) * 2], b1 = b[kt >> 1][(kt & 1) * 2 + 1];
                    mma16816(acc[j][sp], Ah[kt], b0, b1);
                    mma16816(acc[j][sp], Al[kt], b0, b1);
                }
            }
        }
        __syncthreads();
        #pragma unroll
        for (int j = 0; j < 4; j++) {
            int s = ch * 4 + j;
            #pragma unroll
            for (int sp = 0; sp < 2; sp++) {
                int col = s * 16 + sp * 8 + 2 * q;
                float b0 = bps[col], b1 = bps[col + 1];
                int chk = col >> 3;
                #pragma unroll
                for (int rp = 0; rp < 2; rp++) {
                    int row = rg * 16 + r + rp * 8;
                    float v0 = fmaxf(acc[j][sp][rp * 2 + 0] + b0, 0.f);
                    float v1 = fmaxf(acc[j][sp][rp * 2 + 1] + b1, 0.f);
                    __half h0 = __float2half_rn(v0), h1 = __float2half_rn(v1);
                    __half2 hh = __halves2half2(h0, h1);
                    __half2 hl = __halves2half2(__float2half_rn(v0 - __half2float(h0)),
                                                __float2half_rn(v1 - __half2float(h1)));
                    int phys = chk ^ (row & 7);
                    uint32_t off = (uint32_t)(row * 256 + phys * 16 + (col & 7) * 2);
                    *(uint32_t*)(sm + FZ_AH + off) = *(uint32_t*)&hh;
                    *(uint32_t*)(sm + FZ_AL + off) = *(uint32_t*)&hl;
                }
            }
        }
    }
    __syncthreads();

    // ---- GEMM2: G = fp16(xp @ Wih_p^T + bias_p), pair-local layout ----
    uint32_t Ah[8][4], Al[8][4];
    {
        int rowb = rg * 16 + (lane & 7) + ((lane >> 3) & 1) * 8;
        #pragma unroll
        for (int kt = 0; kt < 8; kt++) {
            int chk = 2 * kt + (lane >> 4);
            int phys = chk ^ (rowb & 7);
            ldsm4(ah_u + rowb * 256 + phys * 16, Ah[kt]);
            ldsm4(al_u + rowb * 256 + phys * 16, Al[kt]);
        }
    }
    #pragma unroll
    for (int j = 0; j < 4; j++) {
        const int nb = ch * 4 + j;
        #pragma unroll
        for (int a = 0; a < 4; a++) {
            float acc[2][4] = {};
            #pragma unroll
            for (int sp = 0; sp < 2; sp++) {
                int s = 2 * a + sp;
                int rowb = nb * 64 + s * 8 + (lane & 7);
                uint32_t b[4][4];
                #pragma unroll
                for (int ktp = 0; ktp < 4; ktp++) {
                    int chk = 4 * ktp + (lane >> 3);
                    int phys = chk ^ (rowb & 7);
                    ldsm4(wih_u + rowb * 256 + phys * 16, b[ktp]);
                }
                #pragma unroll
                for (int kt = 0; kt < 8; kt++) {
                    uint32_t b0 = b[kt >> 1][(kt & 1) * 2], b1 = b[kt >> 1][(kt & 1) * 2 + 1];
                    mma16816(acc[sp], Ah[kt], b0, b1);
                    mma16816(acc[sp], Al[kt], b0, b1);
                }
            }
            int colif = nb * 64 + 16 * a + 2 * q;
            float bi = bs[colif], bf = bs[colif + 1], bg = bs[colif + 8], bo = bs[colif + 9];
            #pragma unroll
            for (int rp = 0; rp < 2; rp++) {
                int nl = rg * 16 + r + rp * 8;
                int node = nodeBase + nl;
                if (node < NN) {
                    float iv = acc[0][rp * 2 + 0] + bi;
                    float fv = acc[0][rp * 2 + 1] + bf;
                    float gv = acc[1][rp * 2 + 0] + bg;
                    float ov = acc[1][rp * 2 + 1] + bo;
                    __half2 hif = __floats2half2_rn(iv, fv);
                    __half2 hgo = __floats2half2_rn(gv, ov);
                    size_t base = (size_t)node * 256 + nb * 32 + a * 8 + q * 2;
                    uint2 pv = make_uint2(*(uint32_t*)&hif, *(uint32_t*)&hgo);
                    *(uint2*)(G2 + base) = pv;
                }
            }
        }
    }
}

// ============================================================================
// LSTM aggregation on HMMA — v7: cross-step software pipeline.
// srcs(t+1) prefetched at it=5 of step t; first G block of t+1 prefetched at
// it=7 of step t. Post-add G epilogue, folded sigmoid, vector c (R13).
// SMEM: Whh 128K @0, h 32K @131072, c 64K @163840  => 229376 B
// ============================================================================
#define LS_WHH  0
#define LS_H    131072
#define LS_C    163840
#define LS_SMEM (163840 + 512 * 128)   // 229376

__global__ __launch_bounds__(512, 1) void lstm_mma(
    const __half2* __restrict__ G2, const int* __restrict__ esrc,
    const __half* __restrict__ WhhL, float* __restrict__ aggr)
{
    extern __shared__ char sm[];
    __half* whh = (__half*)(sm + LS_WHH);
    __half* hb  = (__half*)(sm + LS_H);
    const uint32_t whh_u = smem_u32(whh), hb_u = smem_u32(hb);
    const int tid = threadIdx.x, w = tid >> 5, lane = tid & 31;
    const int rg = w & 3, ch = w >> 2;
    const int q = lane & 3, r = lane >> 2;
    const int nodeBase = blockIdx.x * 128;
    char* const cbase = sm + LS_C + tid * 128;   // per-thread 128B c block
    const int cmask = tid & 7;
    // node indices this thread owns (for esrc gather)
    int nodes[4];
    #pragma unroll
    for (int mt2 = 0; mt2 < 2; mt2++)
        #pragma unroll
        for (int rp = 0; rp < 2; rp++)
            nodes[mt2 * 2 + rp] = nodeBase + rg * 32 + mt2 * 16 + r + rp * 8;

    for (int idx = tid; idx < 8192; idx += 512) {
        int row = idx >> 4, chk = idx & 15;
        int phys = chk ^ (row & 7);
        *(uint4*)(whh + row * 128 + phys * 8) = *(const uint4*)(WhhL + row * 128 + chk * 8);
    }
    __syncthreads();

    uint32_t Af[2][8][4];
    int srcs[4], srcsn[4];
    uint2 gp[4], gpn[4];

    // ---- prologue: srcs(t=0) and first G block of t=0 ----
    #pragma unroll
    for (int idx = 0; idx < 4; idx++)
        srcs[idx] = (nodes[idx] < NN) ? __ldg(esrc + (size_t)nodes[idx] * DD) : 0;
    #pragma unroll
    for (int idx = 0; idx < 4; idx++)
        gp[idx] = __ldg((const uint2*)(G2 + (size_t)srcs[idx] * 256 + (ch * 2) * 32 + q * 2));

    for (int t = 0; t < 16; t++) {
        if (t > 0) {
            BARG(rg + 1);
            #pragma unroll
            for (int mt2 = 0; mt2 < 2; mt2++) {
                int rowb = rg * 32 + mt2 * 16 + (lane & 7) + ((lane >> 3) & 1) * 8;
                #pragma unroll
                for (int kt = 0; kt < 8; kt++) {
                    int chk = 2 * kt + (lane >> 4);
                    int phys = chk ^ (rowb & 7);
                    ldsm4(hb_u + rowb * 256 + phys * 16, Af[mt2][kt]);
                }
            }
            BARG(rg + 1);
        }

        #pragma unroll
        for (int it = 0; it < 8; it++) {
            const int j = it >> 2, a = it & 3;
            const int nb = ch * 2 + j;
            // prefetch srcs for t+1 mid-step (esrc is L2-resident)
            if (it == 5 && t < 15) {
                #pragma unroll
                for (int idx = 0; idx < 4; idx++)
                    srcsn[idx] = (nodes[idx] < NN) ? __ldg(esrc + (size_t)nodes[idx] * DD + t + 1) : 0;
            }
            // prefetch next G block: within-step for it<7, cross-step at it==7
            if (it < 7) {
                const int nbn = ch * 2 + ((it + 1) >> 2);
                const int an  = (it + 1) & 3;
                #pragma unroll
                for (int idx = 0; idx < 4; idx++)
                    gpn[idx] = __ldg((const uint2*)(G2 + (size_t)srcs[idx] * 256 + nbn * 32 + an * 8 + q * 2));
            } else if (t < 15) {
                #pragma unroll
                for (int idx = 0; idx < 4; idx++)
                    gpn[idx] = __ldg((const uint2*)(G2 + (size_t)srcsn[idx] * 256 + (ch * 2) * 32 + q * 2));
            }
            float acc[2][2][4] = {};
            if (t > 0) {
                #pragma unroll
                for (int sp = 0; sp < 2; sp++) {
                    int s = 2 * a + sp;
                    int rowb = nb * 64 + s * 8 + (lane & 7);
                    uint32_t b[4][4];
                    #pragma unroll
                    for (int ktp = 0; ktp < 4; ktp++) {
                        int chk = 4 * ktp + (lane >> 3);
                        int phys = chk ^ (rowb & 7);
                        ldsm4(whh_u + rowb * 256 + phys * 16, b[ktp]);
                    }
                    #pragma unroll
                    for (int mt2 = 0; mt2 < 2; mt2++)
                        #pragma unroll
                        for (int kt = 0; kt < 8; kt++)
                            mma16816(acc[sp][mt2], Af[mt2][kt],
                                     b[kt >> 1][(kt & 1) * 2], b[kt >> 1][(kt & 1) * 2 + 1]);
                }
            }
            const int u = nb * 16 + 4 * a + q;
            float4* cp = (float4*)(cbase + ((it ^ cmask) << 4));
            float4 c4;
            if (t > 0) c4 = *cp; else c4 = make_float4(0.f, 0.f, 0.f, 0.f);
            float* c4f = (float*)&c4;
            #pragma unroll
            for (int mt2 = 0; mt2 < 2; mt2++)
                #pragma unroll
                for (int rp = 0; rp < 2; rp++) {
                    int idx = mt2 * 2 + rp;
                    float iv = acc[0][mt2][rp * 2 + 0] + h2lo(gp[idx].x);   // pre-scaled 0.5
                    float fv = acc[0][mt2][rp * 2 + 1] + h2hi(gp[idx].x);   // pre-scaled 0.5
                    float gv = acc[1][mt2][rp * 2 + 0] + h2lo(gp[idx].y);   // unscaled
                    float ov = acc[1][mt2][rp * 2 + 1] + h2hi(gp[idx].y);   // pre-scaled 0.5
                    float cn = sigp(fv) * c4f[idx] + sigp(iv) * tna(gv);
                    c4f[idx] = cn;
                    float h = sigp(ov) * tna(cn);
                    int nl = rg * 32 + mt2 * 16 + r + rp * 8;
                    if (t < 15) {
                        int phys = (u >> 3) ^ (nl & 7);
                        hb[nl * 128 + phys * 8 + (u & 7)] = __float2half_rn(h);
                    } else {
                        int node = nodeBase + nl;
                        if (node < NN) aggr[(size_t)node * FF + u] = h;
                    }
                }
            *cp = c4;
            #pragma unroll
            for (int idx = 0; idx < 4; idx++) gp[idx] = gpn[idx];
        }
        #pragma unroll
        for (int idx = 0; idx < 4; idx++) srcs[idx] = srcsn[idx];
    }
}

// ============================================================================
extern "C" void kernel_launch(void* const* d_in, const int* in_sizes, int n_in,
                              void* d_out, int out_size)
{
    const float* x    = (const float*)d_in[0];
    const int*   esrc = (const int*)d_in[1];
    // d_in[2..7] = dead MLP branch
    const float* Wp1  = (const float*)d_in[8];
    const float* bp1  = (const float*)d_in[9];
    const float* Wih1 = (const float*)d_in[10];
    const float* Whh1 = (const float*)d_in[11];
    const float* bih1 = (const float*)d_in[12];
    const float* bhh1 = (const float*)d_in[13];
    const float* Wl1  = (const float*)d_in[14];
    const float* bl1  = (const float*)d_in[15];
    const float* Wr1  = (const float*)d_in[16];
    const float* Wp2  = (const float*)d_in[17];
    const float* bp2  = (const float*)d_in[18];
    const float* Wih2 = (const float*)d_in[19];
    const float* Whh2 = (const float*)d_in[20];
    const float* bih2 = (const float*)d_in[21];
    const float* bhh2 = (const float*)d_in[22];
    const float* Wl2  = (const float*)d_in[23];
    const float* bl2  = (const float*)d_in[24];
    const float* Wr2  = (const float*)d_in[25];
    float* out = (float*)d_out;

    float *aggr, *h1;
    __half *G, *Whhp, *Wihp, *Wpp;
    float *biasp;
    cudaGetSymbolAddress((void**)&G,     g_G);
    cudaGetSymbolAddress((void**)&aggr,  g_aggr);
    cudaGetSymbolAddress((void**)&h1,    g_h1);
    cudaGetSymbolAddress((void**)&Whhp,  g_Whhp);
    cudaGetSymbolAddress((void**)&Wihp,  g_Wihp);
    cudaGetSymbolAddress((void**)&Wpp,   g_Wpp);
    cudaGetSymbolAddress((void**)&biasp, g_biasp);

    cudaFuncSetAttribute(gfused,   cudaFuncAttributeMaxDynamicSharedMemorySize, FZ_SMEM);
    cudaFuncSetAttribute(lstm_mma, cudaFuncAttributeMaxDynamicSharedMemorySize, LS_SMEM);
    cudaFuncSetAttribute(hgemm<true, true, 8>,  cudaFuncAttributeMaxDynamicSharedMemorySize, HG_SMEM);
    cudaFuncSetAttribute(hgemm<false, true, 4>, cudaFuncAttributeMaxDynamicSharedMemorySize, HG_SMEM);

    const int mblk64  = (NN + 63) / 64;     // 782
    const int mblk128 = (NN + 127) / 128;   // 391

    // ---------- weight prep for BOTH layers, up-front ----------
    prep_permute2<<<dim3(F4, 2), 128>>>(Wih1, Whh1, bih1, bhh1, Wp1,
                                        Wih2, Whh2, bih2, bhh2, Wp2);

    // ---------- layer 1 ----------
    gfused<<<mblk128, 512, FZ_SMEM>>>(x, bp1, Wihp, Wpp, biasp, (__half2*)G);
    lstm_mma<<<mblk128, 512, LS_SMEM>>>((const __half2*)G, esrc, Whhp, aggr);
    hgemm<true, true, 8><<<mblk64, 256, HG_SMEM>>>(aggr, Wl1, x, Wr1, bl1, h1, NN, FF);

    // ---------- layer 2 ----------
    gfused<<<mblk128, 512, FZ_SMEM>>>(h1, bp2, Wihp + (size_t)F4 * FF, Wpp + (size_t)FF * FF,
                                      biasp + F4, (__half2*)G);
    lstm_mma<<<mblk128, 512, LS_SMEM>>>((const __half2*)G, esrc, Whhp + (size_t)F4 * FF, aggr);
    hgemm<false, true, 4><<<mblk64, 256, HG_SMEM>>>(aggr, Wl2, h1, Wr2, bl2, out, NN, CCLS);
}

// round 15
// speedup vs baseline: 1.0259x; 1.0259x over previous
#include <cuda_runtime.h>
#include <cuda_fp16.h>
#include <math.h>
#include <stdint.h>

#define NN   50000
#define DD   16
#define FF   128
#define F4   512
#define CCLS 40

// ---- scratch (device globals: allocation-free rule) ----
__device__ __half g_G[(size_t)NN * F4];       // permuted gate preacts fp16 (51MB, L2-resident)
__device__ float  g_aggr[(size_t)NN * FF];    // LSTM output
__device__ float  g_h1[(size_t)NN * FF];      // layer-1 output
__device__ __half g_Whhp[2][F4 * FF];         // permuted Whh fp16 (i,f,o rows pre-scaled 0.5)
__device__ __half g_Wihp[2][F4 * FF];         // permuted Wih fp16 (i,f,o rows pre-scaled 0.5)
__device__ __half g_Wpp[2][FF * FF];          // projection W fp16
__device__ float  g_biasp[2][F4];             // permuted bih+bhh (i,f,o rows pre-scaled 0.5)
__device__ __half g_Wl1h[FF * FF];            // epilogue weights fp16 (pre-converted)
__device__ __half g_Wr1h[FF * FF];
__device__ __half g_Wl2h[64 * FF];            // zero-padded to 64 rows
__device__ __half g_Wr2h[64 * FF];

// ============================================================================
// helpers
// ============================================================================
__device__ __forceinline__ uint32_t smem_u32(const void* p) {
    uint32_t a;
    asm("{ .reg .u64 t; cvta.to.shared.u64 t, %1; cvt.u32.u64 %0, t; }" : "=r"(a) : "l"(p));
    return a;
}
__device__ __forceinline__ void ldsm4(uint32_t addr, uint32_t r[4]) {
    asm volatile("ldmatrix.sync.aligned.m8n8.x4.shared.b16 {%0,%1,%2,%3}, [%4];"
        : "=r"(r[0]), "=r"(r[1]), "=r"(r[2]), "=r"(r[3]) : "r"(addr));
}
__device__ __forceinline__ void mma16816(float d[4], const uint32_t a[4], uint32_t b0, uint32_t b1) {
    asm volatile("mma.sync.aligned.m16n8k16.row.col.f32.f16.f16.f32 "
        "{%0,%1,%2,%3},{%4,%5,%6,%7},{%8,%9},{%0,%1,%2,%3};"
        : "+f"(d[0]), "+f"(d[1]), "+f"(d[2]), "+f"(d[3])
        : "r"(a[0]), "r"(a[1]), "r"(a[2]), "r"(a[3]), "r"(b0), "r"(b1));
}
__device__ __forceinline__ float tna(float x) { float y; asm("tanh.approx.f32 %0, %1;" : "=f"(y) : "f"(x)); return y; }
// sigmoid with the 1/2 pre-folded into the weights: sig(x) = 0.5 + 0.5*tanh(x_scaled)
__device__ __forceinline__ float sigp(float xs) { return fmaf(tna(xs), 0.5f, 0.5f); }
__device__ __forceinline__ float h2lo(uint32_t v) { __half2 h = *(__half2*)&v; return __low2float(h); }
__device__ __forceinline__ float h2hi(uint32_t v) { __half2 h = *(__half2*)&v; return __high2float(h); }
#define BARG(id) asm volatile("bar.sync %0, 128;" :: "r"(id) : "memory")

// ============================================================================
// Gate-interleave permutation + fp16 conversion of ALL weights — both layers,
// one up-front launch. i,f,o gate rows pre-scaled by 0.5 (exact in fp16).
// ============================================================================
__global__ void prep_permute2(
    const float* __restrict__ Wih1, const float* __restrict__ Whh1,
    const float* __restrict__ bih1, const float* __restrict__ bhh1,
    const float* __restrict__ Wp1,
    const float* __restrict__ Wih2, const float* __restrict__ Whh2,
    const float* __restrict__ bih2, const float* __restrict__ bhh2,
    const float* __restrict__ Wp2,
    const float* __restrict__ Wl1, const float* __restrict__ Wr1,
    const float* __restrict__ Wl2, const float* __restrict__ Wr2)
{
    const int L = blockIdx.y;
    const float* Wih = L ? Wih2 : Wih1;
    const float* Whh = L ? Whh2 : Whh1;
    const float* bih = L ? bih2 : bih1;
    const float* bhh = L ? bhh2 : bhh1;
    const float* Wp  = L ? Wp2  : Wp1;

    int p = blockIdx.x;                 // 0..511 permuted row
    int c = p & 63;
    int nb = p >> 6;
    int c15 = c & 15;
    int g = 2 * ((c15 >> 3) & 1) + (c15 & 1);
    int q = (c15 & 7) >> 1;
    int a = (c >> 4) & 3;
    int u = nb * 16 + 4 * a + q;
    int srow = g * FF + u;              // torch gate order i,f,g,o blocks of 128
    float scale = (g == 2) ? 1.0f : 0.5f;   // i,f,o gates: fold sigmoid's 1/2
    for (int k = threadIdx.x; k < FF; k += blockDim.x) {
        g_Wihp[L][p * FF + k] = __float2half_rn(scale * Wih[srow * FF + k]);
        g_Whhp[L][p * FF + k] = __float2half_rn(scale * Whh[srow * FF + k]);
    }
    if (p < FF)
        for (int k = threadIdx.x; k < FF; k += blockDim.x)
            g_Wpp[L][p * FF + k] = __float2half_rn(Wp[p * FF + k]);
    // epilogue weights
    if (L == 0) {
        if (p < FF)
            for (int k = threadIdx.x; k < FF; k += blockDim.x) {
                g_Wl1h[p * FF + k] = __float2half_rn(Wl1[p * FF + k]);
                g_Wr1h[p * FF + k] = __float2half_rn(Wr1[p * FF + k]);
            }
    } else {
        if (p < 64)
            for (int k = threadIdx.x; k < FF; k += blockDim.x) {
                g_Wl2h[p * FF + k] = (p < CCLS) ? __float2half_rn(Wl2[p * FF + k]) : __float2half_rn(0.f);
                g_Wr2h[p * FF + k] = (p < CCLS) ? __float2half_rn(Wr2[p * FF + k]) : __float2half_rn(0.f);
            }
    }
    if (threadIdx.x == 0) g_biasp[L][p] = scale * (bih[srow] + bhh[srow]);
}

// ============================================================================
// HMMA GEMM: C = act( A@W^T (+ A2@W2^T) + b ), W pre-converted fp16
// (zero-padded). CTA = 64 rows, 256 threads, ~97 KB SMEM -> 2 CTAs/SM.
// ============================================================================
#define HG_W1   0
#define HG_W2   32768
#define HG_A1H  65536
#define HG_A2H  81920
#define HG_BIAS 98304
#define HG_SMEM (98304 + 512 + 128)

template<bool RELU, bool DUAL, int NT>
__global__ __launch_bounds__(256, 2) void hgemm(
    const float* __restrict__ A,  const __half* __restrict__ Wh,
    const float* __restrict__ A2, const __half* __restrict__ W2h,
    const float* __restrict__ bias,
    float* __restrict__ C, int M, int Nout)
{
    extern __shared__ char sm[];
    const int tid = threadIdx.x, w = tid >> 5, lane = tid & 31;
    const int rg = w & 3, ch = w >> 2;            // ch in {0,1}
    const int q = lane & 3, r = lane >> 2;
    const int rowBase = blockIdx.x * 64;

    // ---- stage pre-converted fp16 W (and W2), swizzled (straight copies) ----
    for (int idx = tid; idx < NT * 16 * 16; idx += 256) {
        int row = idx >> 4, chk = idx & 15;
        int phys = chk ^ (row & 7);
        *(uint4*)(sm + HG_W1 + (row * 128 + phys * 8) * 2) = *(const uint4*)(Wh + row * 128 + chk * 8);
        if (DUAL)
            *(uint4*)(sm + HG_W2 + (row * 128 + phys * 8) * 2) = *(const uint4*)(W2h + row * 128 + chk * 8);
    }
    for (int i = tid; i < NT * 16; i += 256)
        *(float*)(sm + HG_BIAS + i * 4) = (i < Nout) ? bias[i] : 0.f;
    for (int idx = tid; idx < 64 * 16; idx += 256) {
        int row = idx >> 4, chk = idx & 15;
        int node = rowBase + row;
        int phys = chk ^ (row & 7);
        #pragma unroll
        for (int p = 0; p < (DUAL ? 2 : 1); p++) {
            const float* Ap = p ? A2 : A;
            __half2 hh[4];
            if (node < M) {
                float4 v0 = *(const float4*)(Ap + (size_t)node * FF + chk * 8);
                float4 v1 = *(const float4*)(Ap + (size_t)node * FF + chk * 8 + 4);
                hh[0] = __floats2half2_rn(v0.x, v0.y);
                hh[1] = __floats2half2_rn(v0.z, v0.w);
                hh[2] = __floats2half2_rn(v1.x, v1.y);
                hh[3] = __floats2half2_rn(v1.z, v1.w);
            } else {
                #pragma unroll
                for (int e = 0; e < 4; e++) hh[e] = __floats2half2_rn(0.f, 0.f);
            }
            *(uint4*)(sm + (p ? HG_A2H : HG_A1H) + (row * 128 + phys * 8) * 2) = *(const uint4*)hh;
        }
    }
    __syncthreads();

    float acc[NT / 2][2][4] = {};
    const int npass = DUAL ? 2 : 1;
    for (int p = 0; p < npass; p++) {
        const uint32_t wu  = smem_u32(sm + (p ? HG_W2  : HG_W1));
        const uint32_t ahu = smem_u32(sm + (p ? HG_A2H : HG_A1H));
        uint32_t Ah[8][4];
        int rowb = rg * 16 + (lane & 7) + ((lane >> 3) & 1) * 8;
        #pragma unroll
        for (int kt = 0; kt < 8; kt++) {
            int chk = 2 * kt + (lane >> 4);
            int phys = chk ^ (rowb & 7);
            ldsm4(ahu + rowb * 256 + phys * 16, Ah[kt]);
        }
        #pragma unroll
        for (int j = 0; j < NT / 2; j++) {
            int s = ch * (NT / 2) + j;
            #pragma unroll
            for (int sp = 0; sp < 2; sp++) {
                int rowbB = s * 16 + sp * 8 + (lane & 7);
                uint32_t b[4][4];
                #pragma unroll
                for (int ktp = 0; ktp < 4; ktp++) {
                    int chk = 4 * ktp + (lane >> 3);
                    int phys = chk ^ (rowbB & 7);
                    ldsm4(wu + rowbB * 256 + phys * 16, b[ktp]);
                }
                #pragma unroll
                for (int kt = 0; kt < 8; kt++)
                    mma16816(acc[j][sp], Ah[kt], b[kt >> 1][(kt & 1) * 2], b[kt >> 1][(kt & 1) * 2 + 1]);
            }
        }
    }

    const float* bs = (const float*)(sm + HG_BIAS);
    #pragma unroll
    for (int j = 0; j < NT / 2; j++) {
        int s = ch * (NT / 2) + j;
        #pragma unroll
        for (int sp = 0; sp < 2; sp++) {
            int col = s * 16 + sp * 8 + 2 * q;
            if (col >= Nout) continue;
            float b0 = bs[col], b1 = bs[col + 1];
            #pragma unroll
            for (int rp = 0; rp < 2; rp++) {
                int row = rowBase + rg * 16 + r + rp * 8;
                if (row >= M) continue;
                float v0 = acc[j][sp][rp * 2 + 0] + b0;
                float v1 = acc[j][sp][rp * 2 + 1] + b1;
                if (RELU) { v0 = fmaxf(v0, 0.f); v1 = fmaxf(v1, 0.f); }
                *(float2*)(C + (size_t)row * Nout + col) = make_float2(v0, v1);
            }
        }
    }
}

// ============================================================================
// FUSED projection + G precompute (HMMA), hi/lo compensated. UNCHANGED (R10).
// ============================================================================
#define FZ_WIH  0
#define FZ_WP   131072
#define FZ_AH   163840
#define FZ_AL   196608
#define FZ_BIAS 229376
#define FZ_BP   231424
#define FZ_SMEM (231424 + 512)

__global__ __launch_bounds__(512, 1) void gfused(
    const float* __restrict__ x, const float* __restrict__ bp,
    const __half* __restrict__ WihL, const __half* __restrict__ WpL,
    const float* __restrict__ biaspL,
    __half2* __restrict__ G2)
{
    extern __shared__ char sm[];
    const uint32_t wih_u = smem_u32(sm + FZ_WIH);
    const uint32_t wp_u  = smem_u32(sm + FZ_WP);
    const uint32_t ah_u  = smem_u32(sm + FZ_AH);
    const uint32_t al_u  = smem_u32(sm + FZ_AL);
    float* bs  = (float*)(sm + FZ_BIAS);
    float* bps = (float*)(sm + FZ_BP);
    const int tid = threadIdx.x, w = tid >> 5, lane = tid & 31;
    const int rg = w & 7, ch = w >> 3;           // rg 0..7 (16-row groups), ch 0..1
    const int q = lane & 3, r = lane >> 2;
    const int nodeBase = blockIdx.x * 128;

    for (int idx = tid; idx < 8192; idx += 512) {
        int row = idx >> 4, chk = idx & 15;
        int phys = chk ^ (row & 7);
        *(uint4*)(sm + FZ_WIH + (row * 128 + phys * 8) * 2) = *(const uint4*)(WihL + row * 128 + chk * 8);
    }
    for (int idx = tid; idx < 2048; idx += 512) {
        int row = idx >> 4, chk = idx & 15;
        int phys = chk ^ (row & 7);
        *(uint4*)(sm + FZ_WP + (row * 128 + phys * 8) * 2) = *(const uint4*)(WpL + row * 128 + chk * 8);
    }
    for (int i = tid; i < F4; i += 512) bs[i] = biaspL[i];
    if (tid < FF) bps[tid] = bp[tid];
    for (int idx = tid; idx < 2048; idx += 512) {
        int row = idx >> 4, chk = idx & 15;
        int node = nodeBase + row;
        float v[8];
        if (node < NN) {
            float4 v0 = *(const float4*)(x + (size_t)node * FF + chk * 8);
            float4 v1 = *(const float4*)(x + (size_t)node * FF + chk * 8 + 4);
            v[0]=v0.x; v[1]=v0.y; v[2]=v0.z; v[3]=v0.w; v[4]=v1.x; v[5]=v1.y; v[6]=v1.z; v[7]=v1.w;
        } else {
            #pragma unroll
            for (int e = 0; e < 8; e++) v[e] = 0.f;
        }
        __half2 hh[4], hl[4];
        #pragma unroll
        for (int e = 0; e < 4; e++) {
            __half h0 = __float2half_rn(v[2*e]), h1 = __float2half_rn(v[2*e+1]);
            hh[e] = __halves2half2(h0, h1);
            hl[e] = __halves2half2(__float2half_rn(v[2*e] - __half2float(h0)),
                                   __float2half_rn(v[2*e+1] - __half2float(h1)));
        }
        int phys = chk ^ (row & 7);
        *(uint4*)(sm + FZ_AH + (row * 128 + phys * 8) * 2) = *(const uint4*)hh;
        *(uint4*)(sm + FZ_AL + (row * 128 + phys * 8) * 2) = *(const uint4*)hl;
    }
    __syncthreads();

    // ---- GEMM1: xp = relu(x @ Wp^T + bp) ----
    {
        uint32_t Ah[8][4], Al[8][4];
        int rowb = rg * 16 + (lane & 7) + ((lane >> 3) & 1) * 8;
        #pragma unroll
        for (int kt = 0; kt < 8; kt++) {
            int chk = 2 * kt + (lane >> 4);
            int phys = chk ^ (rowb & 7);
            ldsm4(ah_u + rowb * 256 + phys * 16, Ah[kt]);
            ldsm4(al_u + rowb * 256 + phys * 16, Al[kt]);
        }
        float acc[4][2][4] = {};
        #pragma unroll
        for (int j = 0; j < 4; j++) {
            int s = ch * 4 + j;
            #pragma unroll
            for (int sp = 0; sp < 2; sp++) {
                int rowbB = s * 16 + sp * 8 + (lane & 7);
                uint32_t b[4][4];
                #pragma unroll
                for (int ktp = 0; ktp < 4; ktp++) {
                    int chk = 4 * ktp + (lane >> 3);
                    int phys = chk ^ (rowbB & 7);
                    ldsm4(wp_u + rowbB * 256 + phys * 16, b[ktp]);
                }
                #pragma unroll
                for (int kt = 0; kt < 8; kt++) {
                    uint32_t b0 = b[kt >> 1][(kt & 1) * 2], b1 = b[kt >> 1][(kt & 1) * 2 + 1];
                    mma16816(acc[j][sp], Ah[kt], b0, b1);
                    mma16816(acc[j][sp], Al[kt], b0, b1);
                }
            }
        }
        __syncthreads();
        #pragma unroll
        for (int j = 0; j < 4; j++) {
            int s = ch * 4 + j;
            #pragma unroll
            for (int sp = 0; sp < 2; sp++) {
                int col = s * 16 + sp * 8 + 2 * q;
                float b0 = bps[col], b1 = bps[col + 1];
                int chk = col >> 3;
                #pragma unroll
                for (int rp = 0; rp < 2; rp++) {
                    int row = rg * 16 + r + rp * 8;
                    float v0 = fmaxf(acc[j][sp][rp * 2 + 0] + b0, 0.f);
                    float v1 = fmaxf(acc[j][sp][rp * 2 + 1] + b1, 0.f);
                    __half h0 = __float2half_rn(v0), h1 = __float2half_rn(v1);
                    __half2 hh = __halves2half2(h0, h1);
                    __half2 hl = __halves2half2(__float2half_rn(v0 - __half2float(h0)),
                                                __float2half_rn(v1 - __half2float(h1)));
                    int phys = chk ^ (row & 7);
                    uint32_t off = (uint32_t)(row * 256 + phys * 16 + (col & 7) * 2);
                    *(uint32_t*)(sm + FZ_AH + off) = *(uint32_t*)&hh;
                    *(uint32_t*)(sm + FZ_AL + off) = *(uint32_t*)&hl;
                }
            }
        }
    }
    __syncthreads();

    // ---- GEMM2: G = fp16(xp @ Wih_p^T + bias_p), pair-local layout ----
    uint32_t Ah[8][4], Al[8][4];
    {
        int rowb = rg * 16 + (lane & 7) + ((lane >> 3) & 1) * 8;
        #pragma unroll
        for (int kt = 0; kt < 8; kt++) {
            int chk = 2 * kt + (lane >> 4);
            int phys = chk ^ (rowb & 7);
            ldsm4(ah_u + rowb * 256 + phys * 16, Ah[kt]);
            ldsm4(al_u + rowb * 256 + phys * 16, Al[kt]);
        }
    }
    #pragma unroll
    for (int j = 0; j < 4; j++) {
        const int nb = ch * 4 + j;
        #pragma unroll
        for (int a = 0; a < 4; a++) {
            float acc[2][4] = {};
            #pragma unroll
            for (int sp = 0; sp < 2; sp++) {
                int s = 2 * a + sp;
                int rowb = nb * 64 + s * 8 + (lane & 7);
                uint32_t b[4][4];
                #pragma unroll
                for (int ktp = 0; ktp < 4; ktp++) {
                    int chk = 4 * ktp + (lane >> 3);
                    int phys = chk ^ (rowb & 7);
                    ldsm4(wih_u + rowb * 256 + phys * 16, b[ktp]);
                }
                #pragma unroll
                for (int kt = 0; kt < 8; kt++) {
                    uint32_t b0 = b[kt >> 1][(kt & 1) * 2], b1 = b[kt >> 1][(kt & 1) * 2 + 1];
                    mma16816(acc[sp], Ah[kt], b0, b1);
                    mma16816(acc[sp], Al[kt], b0, b1);
                }
            }
            int colif = nb * 64 + 16 * a + 2 * q;
            float bi = bs[colif], bf = bs[colif + 1], bg = bs[colif + 8], bo = bs[colif + 9];
            #pragma unroll
            for (int rp = 0; rp < 2; rp++) {
                int nl = rg * 16 + r + rp * 8;
                int node = nodeBase + nl;
                if (node < NN) {
                    float iv = acc[0][rp * 2 + 0] + bi;
                    float fv = acc[0][rp * 2 + 1] + bf;
                    float gv = acc[1][rp * 2 + 0] + bg;
                    float ov = acc[1][rp * 2 + 1] + bo;
                    __half2 hif = __floats2half2_rn(iv, fv);
                    __half2 hgo = __floats2half2_rn(gv, ov);
                    size_t base = (size_t)node * 256 + nb * 32 + a * 8 + q * 2;
                    uint2 pv = make_uint2(*(uint32_t*)&hif, *(uint32_t*)&hgo);
                    *(uint2*)(G2 + base) = pv;
                }
            }
        }
    }
}

// ============================================================================
// LSTM aggregation on HMMA — R13 EXACT (best known: 948 µs config).
// Post-add G, one-iteration-ahead gather prefetch, folded sigmoid, vector c.
// SMEM: Whh 128K @0, h 32K @131072, c 64K @163840  => 229376 B
// ============================================================================
#define LS_WHH  0
#define LS_H    131072
#define LS_C    163840
#define LS_SMEM (163840 + 512 * 128)   // 229376

__global__ __launch_bounds__(512, 1) void lstm_mma(
    const __half2* __restrict__ G2, const int* __restrict__ esrc,
    const __half* __restrict__ WhhL, float* __restrict__ aggr)
{
    extern __shared__ char sm[];
    __half* whh = (__half*)(sm + LS_WHH);
    __half* hb  = (__half*)(sm + LS_H);
    const uint32_t whh_u = smem_u32(whh), hb_u = smem_u32(hb);
    const int tid = threadIdx.x, w = tid >> 5, lane = tid & 31;
    const int rg = w & 3, ch = w >> 2;
    const int q = lane & 3, r = lane >> 2;
    const int nodeBase = blockIdx.x * 128;
    char* const cbase = sm + LS_C + tid * 128;   // per-thread 128B c block
    const int cmask = tid & 7;

    for (int idx = tid; idx < 8192; idx += 512) {
        int row = idx >> 4, chk = idx & 15;
        int phys = chk ^ (row & 7);
        *(uint4*)(whh + row * 128 + phys * 8) = *(const uint4*)(WhhL + row * 128 + chk * 8);
    }
    __syncthreads();

    uint32_t Af[2][8][4];
    int srcs[4];

    for (int t = 0; t < 16; t++) {
        if (t > 0) {
            BARG(rg + 1);
            #pragma unroll
            for (int mt2 = 0; mt2 < 2; mt2++) {
                int rowb = rg * 32 + mt2 * 16 + (lane & 7) + ((lane >> 3) & 1) * 8;
                #pragma unroll
                for (int kt = 0; kt < 8; kt++) {
                    int chk = 2 * kt + (lane >> 4);
                    int phys = chk ^ (rowb & 7);
                    ldsm4(hb_u + rowb * 256 + phys * 16, Af[mt2][kt]);
                }
            }
            BARG(rg + 1);
        }
        #pragma unroll
        for (int mt2 = 0; mt2 < 2; mt2++)
            #pragma unroll
            for (int rp = 0; rp < 2; rp++) {
                int node = nodeBase + rg * 32 + mt2 * 16 + r + rp * 8;
                srcs[mt2 * 2 + rp] = (node < NN) ? __ldg(esrc + (size_t)node * DD + t) : 0;
            }

        // prefetch G for flat-iteration 0 (j=0, a=0)
        uint2 gp[4], gpn[4];
        #pragma unroll
        for (int idx = 0; idx < 4; idx++)
            gp[idx] = __ldg((const uint2*)(G2 + (size_t)srcs[idx] * 256 + (ch * 2) * 32 + q * 2));

        #pragma unroll
        for (int it = 0; it < 8; it++) {
            const int j = it >> 2, a = it & 3;
            const int nb = ch * 2 + j;
            // prefetch next iteration's G (issued before this iteration's MMAs)
            if (it < 7) {
                const int nbn = ch * 2 + ((it + 1) >> 2);
                const int an  = (it + 1) & 3;
                #pragma unroll
                for (int idx = 0; idx < 4; idx++)
                    gpn[idx] = __ldg((const uint2*)(G2 + (size_t)srcs[idx] * 256 + nbn * 32 + an * 8 + q * 2));
            }
            float acc[2][2][4] = {};
            if (t > 0) {
                #pragma unroll
                for (int sp = 0; sp < 2; sp++) {
                    int s = 2 * a + sp;
                    int rowb = nb * 64 + s * 8 + (lane & 7);
                    uint32_t b[4][4];
                    #pragma unroll
                    for (int ktp = 0; ktp < 4; ktp++) {
                        int chk = 4 * ktp + (lane >> 3);
                        int phys = chk ^ (rowb & 7);
                        ldsm4(whh_u + rowb * 256 + phys * 16, b[ktp]);
                    }
                    #pragma unroll
                    for (int mt2 = 0; mt2 < 2; mt2++)
                        #pragma unroll
                        for (int kt = 0; kt < 8; kt++)
                            mma16816(acc[sp][mt2], Af[mt2][kt],
                                     b[kt >> 1][(kt & 1) * 2], b[kt >> 1][(kt & 1) * 2 + 1]);
                }
            }
            const int u = nb * 16 + 4 * a + q;
            float4* cp = (float4*)(cbase + ((it ^ cmask) << 4));
            float4 c4;
            if (t > 0) c4 = *cp; else c4 = make_float4(0.f, 0.f, 0.f, 0.f);
            float* c4f = (float*)&c4;
            #pragma unroll
            for (int mt2 = 0; mt2 < 2; mt2++)
                #pragma unroll
                for (int rp = 0; rp < 2; rp++) {
                    int idx = mt2 * 2 + rp;
                    float iv = acc[0][mt2][rp * 2 + 0] + h2lo(gp[idx].x);   // pre-scaled 0.5
                    float fv = acc[0][mt2][rp * 2 + 1] + h2hi(gp[idx].x);   // pre-scaled 0.5
                    float gv = acc[1][mt2][rp * 2 + 0] + h2lo(gp[idx].y);   // unscaled
                    float ov = acc[1][mt2][rp * 2 + 1] + h2hi(gp[idx].y);   // pre-scaled 0.5
                    float cn = sigp(fv) * c4f[idx] + sigp(iv) * tna(gv);
                    c4f[idx] = cn;
                    float h = sigp(ov) * tna(cn);
                    int nl = rg * 32 + mt2 * 16 + r + rp * 8;
                    if (t < 15) {
                        int phys = (u >> 3) ^ (nl & 7);
                        hb[nl * 128 + phys * 8 + (u & 7)] = __float2half_rn(h);
                    } else {
                        int node = nodeBase + nl;
                        if (node < NN) aggr[(size_t)node * FF + u] = h;
                    }
                }
            *cp = c4;
            #pragma unroll
            for (int idx = 0; idx < 4; idx++) gp[idx] = gpn[idx];
        }
    }
}

// ============================================================================
extern "C" void kernel_launch(void* const* d_in, const int* in_sizes, int n_in,
                              void* d_out, int out_size)
{
    const float* x    = (const float*)d_in[0];
    const int*   esrc = (const int*)d_in[1];
    // d_in[2..7] = dead MLP branch
    const float* Wp1  = (const float*)d_in[8];
    const float* bp1  = (const float*)d_in[9];
    const float* Wih1 = (const float*)d_in[10];
    const float* Whh1 = (const float*)d_in[11];
    const float* bih1 = (const float*)d_in[12];
    const float* bhh1 = (const float*)d_in[13];
    const float* Wl1  = (const float*)d_in[14];
    const float* bl1  = (const float*)d_in[15];
    const float* Wr1  = (const float*)d_in[16];
    const float* Wp2  = (const float*)d_in[17];
    const float* bp2  = (const float*)d_in[18];
    const float* Wih2 = (const float*)d_in[19];
    const float* Whh2 = (const float*)d_in[20];
    const float* bih2 = (const float*)d_in[21];
    const float* bhh2 = (const float*)d_in[22];
    const float* Wl2  = (const float*)d_in[23];
    const float* bl2  = (const float*)d_in[24];
    const float* Wr2  = (const float*)d_in[25];
    float* out = (float*)d_out;

    float *aggr, *h1;
    __half *G, *Whhp, *Wihp, *Wpp, *Wl1h, *Wr1h, *Wl2h, *Wr2h;
    float *biasp;
    cudaGetSymbolAddress((void**)&G,     g_G);
    cudaGetSymbolAddress((void**)&aggr,  g_aggr);
    cudaGetSymbolAddress((void**)&h1,    g_h1);
    cudaGetSymbolAddress((void**)&Whhp,  g_Whhp);
    cudaGetSymbolAddress((void**)&Wihp,  g_Wihp);
    cudaGetSymbolAddress((void**)&Wpp,   g_Wpp);
    cudaGetSymbolAddress((void**)&biasp, g_biasp);
    cudaGetSymbolAddress((void**)&Wl1h,  g_Wl1h);
    cudaGetSymbolAddress((void**)&Wr1h,  g_Wr1h);
    cudaGetSymbolAddress((void**)&Wl2h,  g_Wl2h);
    cudaGetSymbolAddress((void**)&Wr2h,  g_Wr2h);

    cudaFuncSetAttribute(gfused,   cudaFuncAttributeMaxDynamicSharedMemorySize, FZ_SMEM);
    cudaFuncSetAttribute(lstm_mma, cudaFuncAttributeMaxDynamicSharedMemorySize, LS_SMEM);
    cudaFuncSetAttribute(hgemm<true, true, 8>,  cudaFuncAttributeMaxDynamicSharedMemorySize, HG_SMEM);
    cudaFuncSetAttribute(hgemm<false, true, 4>, cudaFuncAttributeMaxDynamicSharedMemorySize, HG_SMEM);

    const int mblk64  = (NN + 63) / 64;     // 782
    const int mblk128 = (NN + 127) / 128;   // 391

    // ---------- weight prep for BOTH layers, up-front ----------
    prep_permute2<<<dim3(F4, 2), 128>>>(Wih1, Whh1, bih1, bhh1, Wp1,
                                        Wih2, Whh2, bih2, bhh2, Wp2,
                                        Wl1, Wr1, Wl2, Wr2);

    // ---------- layer 1 ----------
    gfused<<<mblk128, 512, FZ_SMEM>>>(x, bp1, Wihp, Wpp, biasp, (__half2*)G);
    lstm_mma<<<mblk128, 512, LS_SMEM>>>((const __half2*)G, esrc, Whhp, aggr);
    hgemm<true, true, 8><<<mblk64, 256, HG_SMEM>>>(aggr, Wl1h, x, Wr1h, bl1, h1, NN, FF);

    // ---------- layer 2 ----------
    gfused<<<mblk128, 512, FZ_SMEM>>>(h1, bp2, Wihp + (size_t)F4 * FF, Wpp + (size_t)FF * FF,
                                      biasp + F4, (__half2*)G);
    lstm_mma<<<mblk128, 512, LS_SMEM>>>((const __half2*)G, esrc, Whhp + (size_t)F4 * FF, aggr);
    hgemm<false, true, 4><<<mblk64, 256, HG_SMEM>>>(aggr, Wl2h, h1, Wr2h, bl2, out, NN, CCLS);
}

// round 16
// speedup vs baseline: 1.0304x; 1.0044x over previous
#include <cuda_runtime.h>
#include <cuda_fp16.h>
#include <math.h>
#include <stdint.h>

#define NN   50000
#define DD   16
#define FF   128
#define F4   512
#define CCLS 40

// ---- scratch (device globals: allocation-free rule) ----
__device__ __half g_G[(size_t)NN * F4];       // permuted gate preacts fp16 (51MB, L2-resident)
__device__ __half g_aggr[(size_t)NN * FF];    // LSTM output (fp16 — consumed only as MMA A-operand)
__device__ float  g_h1[(size_t)NN * FF];      // layer-1 output (fp32 — gfused needs hi/lo)
__device__ __half g_Whhp[2][F4 * FF];         // permuted Whh fp16 (i,f,o rows pre-scaled 0.5)
__device__ __half g_Wihp[2][F4 * FF];         // permuted Wih fp16 (i,f,o rows pre-scaled 0.5)
__device__ __half g_Wpp[2][FF * FF];          // projection W fp16
__device__ float  g_biasp[2][F4];             // permuted bih+bhh (i,f,o rows pre-scaled 0.5)
__device__ __half g_Wl1h[FF * FF];            // epilogue weights fp16 (pre-converted)
__device__ __half g_Wr1h[FF * FF];
__device__ __half g_Wl2h[64 * FF];            // zero-padded to 64 rows
__device__ __half g_Wr2h[64 * FF];

// ============================================================================
// helpers
// ============================================================================
__device__ __forceinline__ uint32_t smem_u32(const void* p) {
    uint32_t a;
    asm("{ .reg .u64 t; cvta.to.shared.u64 t, %1; cvt.u32.u64 %0, t; }" : "=r"(a) : "l"(p));
    return a;
}
__device__ __forceinline__ void ldsm4(uint32_t addr, uint32_t r[4]) {
    asm volatile("ldmatrix.sync.aligned.m8n8.x4.shared.b16 {%0,%1,%2,%3}, [%4];"
        : "=r"(r[0]), "=r"(r[1]), "=r"(r[2]), "=r"(r[3]) : "r"(addr));
}
__device__ __forceinline__ void mma16816(float d[4], const uint32_t a[4], uint32_t b0, uint32_t b1) {
    asm volatile("mma.sync.aligned.m16n8k16.row.col.f32.f16.f16.f32 "
        "{%0,%1,%2,%3},{%4,%5,%6,%7},{%8,%9},{%0,%1,%2,%3};"
        : "+f"(d[0]), "+f"(d[1]), "+f"(d[2]), "+f"(d[3])
        : "r"(a[0]), "r"(a[1]), "r"(a[2]), "r"(a[3]), "r"(b0), "r"(b1));
}
__device__ __forceinline__ float tna(float x) { float y; asm("tanh.approx.f32 %0, %1;" : "=f"(y) : "f"(x)); return y; }
// sigmoid with the 1/2 pre-folded into the weights: sig(x) = 0.5 + 0.5*tanh(x_scaled)
__device__ __forceinline__ float sigp(float xs) { return fmaf(tna(xs), 0.5f, 0.5f); }
__device__ __forceinline__ float h2lo(uint32_t v) { __half2 h = *(__half2*)&v; return __low2float(h); }
__device__ __forceinline__ float h2hi(uint32_t v) { __half2 h = *(__half2*)&v; return __high2float(h); }
#define BARG(id) asm volatile("bar.sync %0, 128;" :: "r"(id) : "memory")

// ============================================================================
// Gate-interleave permutation + fp16 conversion of ALL weights — both layers,
// one up-front launch. i,f,o gate rows pre-scaled by 0.5 (exact in fp16).
// ============================================================================
__global__ void prep_permute2(
    const float* __restrict__ Wih1, const float* __restrict__ Whh1,
    const float* __restrict__ bih1, const float* __restrict__ bhh1,
    const float* __restrict__ Wp1,
    const float* __restrict__ Wih2, const float* __restrict__ Whh2,
    const float* __restrict__ bih2, const float* __restrict__ bhh2,
    const float* __restrict__ Wp2,
    const float* __restrict__ Wl1, const float* __restrict__ Wr1,
    const float* __restrict__ Wl2, const float* __restrict__ Wr2)
{
    const int L = blockIdx.y;
    const float* Wih = L ? Wih2 : Wih1;
    const float* Whh = L ? Whh2 : Whh1;
    const float* bih = L ? bih2 : bih1;
    const float* bhh = L ? bhh2 : bhh1;
    const float* Wp  = L ? Wp2  : Wp1;

    int p = blockIdx.x;                 // 0..511 permuted row
    int c = p & 63;
    int nb = p >> 6;
    int c15 = c & 15;
    int g = 2 * ((c15 >> 3) & 1) + (c15 & 1);
    int q = (c15 & 7) >> 1;
    int a = (c >> 4) & 3;
    int u = nb * 16 + 4 * a + q;
    int srow = g * FF + u;              // torch gate order i,f,g,o blocks of 128
    float scale = (g == 2) ? 1.0f : 0.5f;   // i,f,o gates: fold sigmoid's 1/2
    for (int k = threadIdx.x; k < FF; k += blockDim.x) {
        g_Wihp[L][p * FF + k] = __float2half_rn(scale * Wih[srow * FF + k]);
        g_Whhp[L][p * FF + k] = __float2half_rn(scale * Whh[srow * FF + k]);
    }
    if (p < FF)
        for (int k = threadIdx.x; k < FF; k += blockDim.x)
            g_Wpp[L][p * FF + k] = __float2half_rn(Wp[p * FF + k]);
    // epilogue weights
    if (L == 0) {
        if (p < FF)
            for (int k = threadIdx.x; k < FF; k += blockDim.x) {
                g_Wl1h[p * FF + k] = __float2half_rn(Wl1[p * FF + k]);
                g_Wr1h[p * FF + k] = __float2half_rn(Wr1[p * FF + k]);
            }
    } else {
        if (p < 64)
            for (int k = threadIdx.x; k < FF; k += blockDim.x) {
                g_Wl2h[p * FF + k] = (p < CCLS) ? __float2half_rn(Wl2[p * FF + k]) : __float2half_rn(0.f);
                g_Wr2h[p * FF + k] = (p < CCLS) ? __float2half_rn(Wr2[p * FF + k]) : __float2half_rn(0.f);
            }
    }
    if (threadIdx.x == 0) g_biasp[L][p] = scale * (bih[srow] + bhh[srow]);
}

// ============================================================================
// HMMA GEMM: C = act( A@W^T + A2@W2^T + b ), A fp16 (straight copy),
// A2 fp32 (convert), W/W2 pre-converted fp16 zero-padded.
// CTA = 64 rows, 256 threads, ~81 KB SMEM -> 2 CTAs/SM.
// ============================================================================
#define HG_W1   0
#define HG_W2   32768
#define HG_A1H  65536
#define HG_A2H  81920
#define HG_BIAS 98304
#define HG_SMEM (98304 + 512 + 128)

template<bool RELU, int NT>
__global__ __launch_bounds__(256, 2) void hgemm(
    const __half* __restrict__ A,  const __half* __restrict__ Wh,
    const float*  __restrict__ A2, const __half* __restrict__ W2h,
    const float*  __restrict__ bias,
    float* __restrict__ C, int M, int Nout)
{
    extern __shared__ char sm[];
    const int tid = threadIdx.x, w = tid >> 5, lane = tid & 31;
    const int rg = w & 3, ch = w >> 2;            // ch in {0,1}
    const int q = lane & 3, r = lane >> 2;
    const int rowBase = blockIdx.x * 64;

    // ---- stage pre-converted fp16 W + W2, swizzled (straight copies) ----
    for (int idx = tid; idx < NT * 16 * 16; idx += 256) {
        int row = idx >> 4, chk = idx & 15;
        int phys = chk ^ (row & 7);
        *(uint4*)(sm + HG_W1 + (row * 128 + phys * 8) * 2) = *(const uint4*)(Wh + row * 128 + chk * 8);
        *(uint4*)(sm + HG_W2 + (row * 128 + phys * 8) * 2) = *(const uint4*)(W2h + row * 128 + chk * 8);
    }
    for (int i = tid; i < NT * 16; i += 256)
        *(float*)(sm + HG_BIAS + i * 4) = (i < Nout) ? bias[i] : 0.f;
    // ---- stage A (fp16 straight copy) and A2 (fp32 convert) ----
    for (int idx = tid; idx < 64 * 16; idx += 256) {
        int row = idx >> 4, chk = idx & 15;
        int node = rowBase + row;
        int phys = chk ^ (row & 7);
        uint4 a1;
        __half2 hh[4];
        if (node < M) {
            a1 = *(const uint4*)(A + (size_t)node * FF + chk * 8);
            float4 v0 = *(const float4*)(A2 + (size_t)node * FF + chk * 8);
            float4 v1 = *(const float4*)(A2 + (size_t)node * FF + chk * 8 + 4);
            hh[0] = __floats2half2_rn(v0.x, v0.y);
            hh[1] = __floats2half2_rn(v0.z, v0.w);
            hh[2] = __floats2half2_rn(v1.x, v1.y);
            hh[3] = __floats2half2_rn(v1.z, v1.w);
        } else {
            a1 = make_uint4(0, 0, 0, 0);
            #pragma unroll
            for (int e = 0; e < 4; e++) hh[e] = __floats2half2_rn(0.f, 0.f);
        }
        *(uint4*)(sm + HG_A1H + (row * 128 + phys * 8) * 2) = a1;
        *(uint4*)(sm + HG_A2H + (row * 128 + phys * 8) * 2) = *(const uint4*)hh;
    }
    __syncthreads();

    float acc[NT / 2][2][4] = {};
    #pragma unroll
    for (int p = 0; p < 2; p++) {
        const uint32_t wu  = smem_u32(sm + (p ? HG_W2  : HG_W1));
        const uint32_t ahu = smem_u32(sm + (p ? HG_A2H : HG_A1H));
        uint32_t Ah[8][4];
        int rowb = rg * 16 + (lane & 7) + ((lane >> 3) & 1) * 8;
        #pragma unroll
        for (int kt = 0; kt < 8; kt++) {
            int chk = 2 * kt + (lane >> 4);
            int phys = chk ^ (rowb & 7);
            ldsm4(ahu + rowb * 256 + phys * 16, Ah[kt]);
        }
        #pragma unroll
        for (int j = 0; j < NT / 2; j++) {
            int s = ch * (NT / 2) + j;
            #pragma unroll
            for (int sp = 0; sp < 2; sp++) {
                int rowbB = s * 16 + sp * 8 + (lane & 7);
                uint32_t b[4][4];
                #pragma unroll
                for (int ktp = 0; ktp < 4; ktp++) {
                    int chk = 4 * ktp + (lane >> 3);
                    int phys = chk ^ (rowbB & 7);
                    ldsm4(wu + rowbB * 256 + phys * 16, b[ktp]);
                }
                #pragma unroll
                for (int kt = 0; kt < 8; kt++)
                    mma16816(acc[j][sp], Ah[kt], b[kt >> 1][(kt & 1) * 2], b[kt >> 1][(kt & 1) * 2 + 1]);
            }
        }
    }

    const float* bs = (const float*)(sm + HG_BIAS);
    #pragma unroll
    for (int j = 0; j < NT / 2; j++) {
        int s = ch * (NT / 2) + j;
        #pragma unroll
        for (int sp = 0; sp < 2; sp++) {
            int col = s * 16 + sp * 8 + 2 * q;
            if (col >= Nout) continue;
            float b0 = bs[col], b1 = bs[col + 1];
            #pragma unroll
            for (int rp = 0; rp < 2; rp++) {
                int row = rowBase + rg * 16 + r + rp * 8;
                if (row >= M) continue;
                float v0 = acc[j][sp][rp * 2 + 0] + b0;
                float v1 = acc[j][sp][rp * 2 + 1] + b1;
                if (RELU) { v0 = fmaxf(v0, 0.f); v1 = fmaxf(v1, 0.f); }
                *(float2*)(C + (size_t)row * Nout + col) = make_float2(v0, v1);
            }
        }
    }
}

// ============================================================================
// FUSED projection + G precompute (HMMA), hi/lo compensated. UNCHANGED (R10).
// ============================================================================
#define FZ_WIH  0
#define FZ_WP   131072
#define FZ_AH   163840
#define FZ_AL   196608
#define FZ_BIAS 229376
#define FZ_BP   231424
#define FZ_SMEM (231424 + 512)

__global__ __launch_bounds__(512, 1) void gfused(
    const float* __restrict__ x, const float* __restrict__ bp,
    const __half* __restrict__ WihL, const __half* __restrict__ WpL,
    const float* __restrict__ biaspL,
    __half2* __restrict__ G2)
{
    extern __shared__ char sm[];
    const uint32_t wih_u = smem_u32(sm + FZ_WIH);
    const uint32_t wp_u  = smem_u32(sm + FZ_WP);
    const uint32_t ah_u  = smem_u32(sm + FZ_AH);
    const uint32_t al_u  = smem_u32(sm + FZ_AL);
    float* bs  = (float*)(sm + FZ_BIAS);
    float* bps = (float*)(sm + FZ_BP);
    const int tid = threadIdx.x, w = tid >> 5, lane = tid & 31;
    const int rg = w & 7, ch = w >> 3;           // rg 0..7 (16-row groups), ch 0..1
    const int q = lane & 3, r = lane >> 2;
    const int nodeBase = blockIdx.x * 128;

    for (int idx = tid; idx < 8192; idx += 512) {
        int row = idx >> 4, chk = idx & 15;
        int phys = chk ^ (row & 7);
        *(uint4*)(sm + FZ_WIH + (row * 128 + phys * 8) * 2) = *(const uint4*)(WihL + row * 128 + chk * 8);
    }
    for (int idx = tid; idx < 2048; idx += 512) {
        int row = idx >> 4, chk = idx & 15;
        int phys = chk ^ (row & 7);
        *(uint4*)(sm + FZ_WP + (row * 128 + phys * 8) * 2) = *(const uint4*)(WpL + row * 128 + chk * 8);
    }
    for (int i = tid; i < F4; i += 512) bs[i] = biaspL[i];
    if (tid < FF) bps[tid] = bp[tid];
    for (int idx = tid; idx < 2048; idx += 512) {
        int row = idx >> 4, chk = idx & 15;
        int node = nodeBase + row;
        float v[8];
        if (node < NN) {
            float4 v0 = *(const float4*)(x + (size_t)node * FF + chk * 8);
            float4 v1 = *(const float4*)(x + (size_t)node * FF + chk * 8 + 4);
            v[0]=v0.x; v[1]=v0.y; v[2]=v0.z; v[3]=v0.w; v[4]=v1.x; v[5]=v1.y; v[6]=v1.z; v[7]=v1.w;
        } else {
            #pragma unroll
            for (int e = 0; e < 8; e++) v[e] = 0.f;
        }
        __half2 hh[4], hl[4];
        #pragma unroll
        for (int e = 0; e < 4; e++) {
            __half h0 = __float2half_rn(v[2*e]), h1 = __float2half_rn(v[2*e+1]);
            hh[e] = __halves2half2(h0, h1);
            hl[e] = __halves2half2(__float2half_rn(v[2*e] - __half2float(h0)),
                                   __float2half_rn(v[2*e+1] - __half2float(h1)));
        }
        int phys = chk ^ (row & 7);
        *(uint4*)(sm + FZ_AH + (row * 128 + phys * 8) * 2) = *(const uint4*)hh;
        *(uint4*)(sm + FZ_AL + (row * 128 + phys * 8) * 2) = *(const uint4*)hl;
    }
    __syncthreads();

    // ---- GEMM1: xp = relu(x @ Wp^T + bp) ----
    {
        uint32_t Ah[8][4], Al[8][4];
        int rowb = rg * 16 + (lane & 7) + ((lane >> 3) & 1) * 8;
        #pragma unroll
        for (int kt = 0; kt < 8; kt++) {
            int chk = 2 * kt + (lane >> 4);
            int phys = chk ^ (rowb & 7);
            ldsm4(ah_u + rowb * 256 + phys * 16, Ah[kt]);
            ldsm4(al_u + rowb * 256 + phys * 16, Al[kt]);
        }
        float acc[4][2][4] = {};
        #pragma unroll
        for (int j = 0; j < 4; j++) {
            int s = ch * 4 + j;
            #pragma unroll
            for (int sp = 0; sp < 2; sp++) {
                int rowbB = s * 16 + sp * 8 + (lane & 7);
                uint32_t b[4][4];
                #pragma unroll
                for (int ktp = 0; ktp < 4; ktp++) {
                    int chk = 4 * ktp + (lane >> 3);
                    int phys = chk ^ (rowbB & 7);
                    ldsm4(wp_u + rowbB * 256 + phys * 16, b[ktp]);
                }
                #pragma unroll
                for (int kt = 0; kt < 8; kt++) {
                    uint32_t b0 = b[kt >> 1][(kt & 1) * 2], b1 = b[kt >> 1][(kt & 1) * 2 + 1];
                    mma16816(acc[j][sp], Ah[kt], b0, b1);
                    mma16816(acc[j][sp], Al[kt], b0, b1);
                }
            }
        }
        __syncthreads();
        #pragma unroll
        for (int j = 0; j < 4; j++) {
            int s = ch * 4 + j;
            #pragma unroll
            for (int sp = 0; sp < 2; sp++) {
                int col = s * 16 + sp * 8 + 2 * q;
                float b0 = bps[col], b1 = bps[col + 1];
                int chk = col >> 3;
                #pragma unroll
                for (int rp = 0; rp < 2; rp++) {
                    int row = rg * 16 + r + rp * 8;
                    float v0 = fmaxf(acc[j][sp][rp * 2 + 0] + b0, 0.f);
                    float v1 = fmaxf(acc[j][sp][rp * 2 + 1] + b1, 0.f);
                    __half h0 = __float2half_rn(v0), h1 = __float2half_rn(v1);
                    __half2 hh = __halves2half2(h0, h1);
                    __half2 hl = __halves2half2(__float2half_rn(v0 - __half2float(h0)),
                                                __float2half_rn(v1 - __half2float(h1)));
                    int phys = chk ^ (row & 7);
                    uint32_t off = (uint32_t)(row * 256 + phys * 16 + (col & 7) * 2);
                    *(uint32_t*)(sm + FZ_AH + off) = *(uint32_t*)&hh;
                    *(uint32_t*)(sm + FZ_AL + off) = *(uint32_t*)&hl;
                }
            }
        }
    }
    __syncthreads();

    // ---- GEMM2: G = fp16(xp @ Wih_p^T + bias_p), pair-local layout ----
    uint32_t Ah[8][4], Al[8][4];
    {
        int rowb = rg * 16 + (lane & 7) + ((lane >> 3) & 1) * 8;
        #pragma unroll
        for (int kt = 0; kt < 8; kt++) {
            int chk = 2 * kt + (lane >> 4);
            int phys = chk ^ (rowb & 7);
            ldsm4(ah_u + rowb * 256 + phys * 16, Ah[kt]);
            ldsm4(al_u + rowb * 256 + phys * 16, Al[kt]);
        }
    }
    #pragma unroll
    for (int j = 0; j < 4; j++) {
        const int nb = ch * 4 + j;
        #pragma unroll
        for (int a = 0; a < 4; a++) {
            float acc[2][4] = {};
            #pragma unroll
            for (int sp = 0; sp < 2; sp++) {
                int s = 2 * a + sp;
                int rowb = nb * 64 + s * 8 + (lane & 7);
                uint32_t b[4][4];
                #pragma unroll
                for (int ktp = 0; ktp < 4; ktp++) {
                    int chk = 4 * ktp + (lane >> 3);
                    int phys = chk ^ (rowb & 7);
                    ldsm4(wih_u + rowb * 256 + phys * 16, b[ktp]);
                }
                #pragma unroll
                for (int kt = 0; kt < 8; kt++) {
                    uint32_t b0 = b[kt >> 1][(kt & 1) * 2], b1 = b[kt >> 1][(kt & 1) * 2 + 1];
                    mma16816(acc[sp], Ah[kt], b0, b1);
                    mma16816(acc[sp], Al[kt], b0, b1);
                }
            }
            int colif = nb * 64 + 16 * a + 2 * q;
            float bi = bs[colif], bf = bs[colif + 1], bg = bs[colif + 8], bo = bs[colif + 9];
            #pragma unroll
            for (int rp = 0; rp < 2; rp++) {
                int nl = rg * 16 + r + rp * 8;
                int node = nodeBase + nl;
                if (node < NN) {
                    float iv = acc[0][rp * 2 + 0] + bi;
                    float fv = acc[0][rp * 2 + 1] + bf;
                    float gv = acc[1][rp * 2 + 0] + bg;
                    float ov = acc[1][rp * 2 + 1] + bo;
                    __half2 hif = __floats2half2_rn(iv, fv);
                    __half2 hgo = __floats2half2_rn(gv, ov);
                    size_t base = (size_t)node * 256 + nb * 32 + a * 8 + q * 2;
                    uint2 pv = make_uint2(*(uint32_t*)&hif, *(uint32_t*)&hgo);
                    *(uint2*)(G2 + base) = pv;
                }
            }
        }
    }
}

// ============================================================================
// LSTM aggregation on HMMA — R13 structure (best known); aggr now fp16
// (same __float2half_rn the consumer previously applied).
// SMEM: Whh 128K @0, h 32K @131072, c 64K @163840  => 229376 B
// ============================================================================
#define LS_WHH  0
#define LS_H    131072
#define LS_C    163840
#define LS_SMEM (163840 + 512 * 128)   // 229376

__global__ __launch_bounds__(512, 1) void lstm_mma(
    const __half2* __restrict__ G2, const int* __restrict__ esrc,
    const __half* __restrict__ WhhL, __half* __restrict__ aggr)
{
    extern __shared__ char sm[];
    __half* whh = (__half*)(sm + LS_WHH);
    __half* hb  = (__half*)(sm + LS_H);
    const uint32_t whh_u = smem_u32(whh), hb_u = smem_u32(hb);
    const int tid = threadIdx.x, w = tid >> 5, lane = tid & 31;
    const int rg = w & 3, ch = w >> 2;
    const int q = lane & 3, r = lane >> 2;
    const int nodeBase = blockIdx.x * 128;
    char* const cbase = sm + LS_C + tid * 128;   // per-thread 128B c block
    const int cmask = tid & 7;

    for (int idx = tid; idx < 8192; idx += 512) {
        int row = idx >> 4, chk = idx & 15;
        int phys = chk ^ (row & 7);
        *(uint4*)(whh + row * 128 + phys * 8) = *(const uint4*)(WhhL + row * 128 + chk * 8);
    }
    __syncthreads();

    uint32_t Af[2][8][4];
    int srcs[4];

    for (int t = 0; t < 16; t++) {
        if (t > 0) {
            BARG(rg + 1);
            #pragma unroll
            for (int mt2 = 0; mt2 < 2; mt2++) {
                int rowb = rg * 32 + mt2 * 16 + (lane & 7) + ((lane >> 3) & 1) * 8;
                #pragma unroll
                for (int kt = 0; kt < 8; kt++) {
                    int chk = 2 * kt + (lane >> 4);
                    int phys = chk ^ (rowb & 7);
                    ldsm4(hb_u + rowb * 256 + phys * 16, Af[mt2][kt]);
                }
            }
            BARG(rg + 1);
        }
        #pragma unroll
        for (int mt2 = 0; mt2 < 2; mt2++)
            #pragma unroll
            for (int rp = 0; rp < 2; rp++) {
                int node = nodeBase + rg * 32 + mt2 * 16 + r + rp * 8;
                srcs[mt2 * 2 + rp] = (node < NN) ? __ldg(esrc + (size_t)node * DD + t) : 0;
            }

        // prefetch G for flat-iteration 0 (j=0, a=0)
        uint2 gp[4], gpn[4];
        #pragma unroll
        for (int idx = 0; idx < 4; idx++)
            gp[idx] = __ldg((const uint2*)(G2 + (size_t)srcs[idx] * 256 + (ch * 2) * 32 + q * 2));

        #pragma unroll
        for (int it = 0; it < 8; it++) {
            const int j = it >> 2, a = it & 3;
            const int nb = ch * 2 + j;
            // prefetch next iteration's G (issued before this iteration's MMAs)
            if (it < 7) {
                const int nbn = ch * 2 + ((it + 1) >> 2);
                const int an  = (it + 1) & 3;
                #pragma unroll
                for (int idx = 0; idx < 4; idx++)
                    gpn[idx] = __ldg((const uint2*)(G2 + (size_t)srcs[idx] * 256 + nbn * 32 + an * 8 + q * 2));
            }
            float acc[2][2][4] = {};
            if (t > 0) {
                #pragma unroll
                for (int sp = 0; sp < 2; sp++) {
                    int s = 2 * a + sp;
                    int rowb = nb * 64 + s * 8 + (lane & 7);
                    uint32_t b[4][4];
                    #pragma unroll
                    for (int ktp = 0; ktp < 4; ktp++) {
                        int chk = 4 * ktp + (lane >> 3);
                        int phys = chk ^ (rowb & 7);
                        ldsm4(whh_u + rowb * 256 + phys * 16, b[ktp]);
                    }
                    #pragma unroll
                    for (int mt2 = 0; mt2 < 2; mt2++)
                        #pragma unroll
                        for (int kt = 0; kt < 8; kt++)
                            mma16816(acc[sp][mt2], Af[mt2][kt],
                                     b[kt >> 1][(kt & 1) * 2], b[kt >> 1][(kt & 1) * 2 + 1]);
                }
            }
            const int u = nb * 16 + 4 * a + q;
            float4* cp = (float4*)(cbase + ((it ^ cmask) << 4));
            float4 c4;
            if (t > 0) c4 = *cp; else c4 = make_float4(0.f, 0.f, 0.f, 0.f);
            float* c4f = (float*)&c4;
            #pragma unroll
            for (int mt2 = 0; mt2 < 2; mt2++)
                #pragma unroll
                for (int rp = 0; rp < 2; rp++) {
                    int idx = mt2 * 2 + rp;
                    float iv = acc[0][mt2][rp * 2 + 0] + h2lo(gp[idx].x);   // pre-scaled 0.5
                    float fv = acc[0][mt2][rp * 2 + 1] + h2hi(gp[idx].x);   // pre-scaled 0.5
                    float gv = acc[1][mt2][rp * 2 + 0] + h2lo(gp[idx].y);   // unscaled
                    float ov = acc[1][mt2][rp * 2 + 1] + h2hi(gp[idx].y);   // pre-scaled 0.5
                    float cn = sigp(fv) * c4f[idx] + sigp(iv) * tna(gv);
                    c4f[idx] = cn;
                    float h = sigp(ov) * tna(cn);
                    int nl = rg * 32 + mt2 * 16 + r + rp * 8;
                    if (t < 15) {
                        int phys = (u >> 3) ^ (nl & 7);
                        hb[nl * 128 + phys * 8 + (u & 7)] = __float2half_rn(h);
                    } else {
                        int node = nodeBase + nl;
                        if (node < NN) aggr[(size_t)node * FF + u] = __float2half_rn(h);
                    }
                }
            *cp = c4;
            #pragma unroll
            for (int idx = 0; idx < 4; idx++) gp[idx] = gpn[idx];
        }
    }
}

// ============================================================================
extern "C" void kernel_launch(void* const* d_in, const int* in_sizes, int n_in,
                              void* d_out, int out_size)
{
    const float* x    = (const float*)d_in[0];
    const int*   esrc = (const int*)d_in[1];
    // d_in[2..7] = dead MLP branch
    const float* Wp1  = (const float*)d_in[8];
    const float* bp1  = (const float*)d_in[9];
    const float* Wih1 = (const float*)d_in[10];
    const float* Whh1 = (const float*)d_in[11];
    const float* bih1 = (const float*)d_in[12];
    const float* bhh1 = (const float*)d_in[13];
    const float* Wl1  = (const float*)d_in[14];
    const float* bl1  = (const float*)d_in[15];
    const float* Wr1  = (const float*)d_in[16];
    const float* Wp2  = (const float*)d_in[17];
    const float* bp2  = (const float*)d_in[18];
    const float* Wih2 = (const float*)d_in[19];
    const float* Whh2 = (const float*)d_in[20];
    const float* bih2 = (const float*)d_in[21];
    const float* bhh2 = (const float*)d_in[22];
    const float* Wl2  = (const float*)d_in[23];
    const float* bl2  = (const float*)d_in[24];
    const float* Wr2  = (const float*)d_in[25];
    float* out = (float*)d_out;

    float *h1, *biasp;
    __half *G, *aggr, *Whhp, *Wihp, *Wpp, *Wl1h, *Wr1h, *Wl2h, *Wr2h;
    cudaGetSymbolAddress((void**)&G,     g_G);
    cudaGetSymbolAddress((void**)&aggr,  g_aggr);
    cudaGetSymbolAddress((void**)&h1,    g_h1);
    cudaGetSymbolAddress((void**)&Whhp,  g_Whhp);
    cudaGetSymbolAddress((void**)&Wihp,  g_Wihp);
    cudaGetSymbolAddress((void**)&Wpp,   g_Wpp);
    cudaGetSymbolAddress((void**)&biasp, g_biasp);
    cudaGetSymbolAddress((void**)&Wl1h,  g_Wl1h);
    cudaGetSymbolAddress((void**)&Wr1h,  g_Wr1h);
    cudaGetSymbolAddress((void**)&Wl2h,  g_Wl2h);
    cudaGetSymbolAddress((void**)&Wr2h,  g_Wr2h);

    cudaFuncSetAttribute(gfused,   cudaFuncAttributeMaxDynamicSharedMemorySize, FZ_SMEM);
    cudaFuncSetAttribute(lstm_mma, cudaFuncAttributeMaxDynamicSharedMemorySize, LS_SMEM);
    cudaFuncSetAttribute(hgemm<true, 8>,  cudaFuncAttributeMaxDynamicSharedMemorySize, HG_SMEM);
    cudaFuncSetAttribute(hgemm<false, 4>, cudaFuncAttributeMaxDynamicSharedMemorySize, HG_SMEM);

    const int mblk64  = (NN + 63) / 64;     // 782
    const int mblk128 = (NN + 127) / 128;   // 391

    // ---------- weight prep for BOTH layers, up-front ----------
    prep_permute2<<<dim3(F4, 2), 128>>>(Wih1, Whh1, bih1, bhh1, Wp1,
                                        Wih2, Whh2, bih2, bhh2, Wp2,
                                        Wl1, Wr1, Wl2, Wr2);

    // ---------- layer 1 ----------
    gfused<<<mblk128, 512, FZ_SMEM>>>(x, bp1, Wihp, Wpp, biasp, (__half2*)G);
    lstm_mma<<<mblk128, 512, LS_SMEM>>>((const __half2*)G, esrc, Whhp, aggr);
    hgemm<true, 8><<<mblk64, 256, HG_SMEM>>>(aggr, Wl1h, x, Wr1h, bl1, h1, NN, FF);

    // ---------- layer 2 ----------
    gfused<<<mblk128, 512, FZ_SMEM>>>(h1, bp2, Wihp + (size_t)F4 * FF, Wpp + (size_t)FF * FF,
                                      biasp + F4, (__half2*)G);
    lstm_mma<<<mblk128, 512, LS_SMEM>>>((const __half2*)G, esrc, Whhp + (size_t)F4 * FF, aggr);
    hgemm<false, 4><<<mblk64, 256, HG_SMEM>>>(aggr, Wl2h, h1, Wr2h, bl2, out, NN, CCLS);
}